// round 1
// baseline (speedup 1.0000x reference)
#include <cuda_runtime.h>

#define IN_F   64
#define OUT_F  100
#define MAX_NODES 100000

// Scratch (allocation-free rule: device globals)
__device__ float g_S[(size_t)MAX_NODES * IN_F];   // segment sums [n_nodes, 64]
__device__ float g_deg[MAX_NODES];                // in-degree per node

// ---------------------------------------------------------------------------
// Kernel 1: zero scratch
// ---------------------------------------------------------------------------
__global__ void zero_kernel(int n_nodes) {
    int i = blockIdx.x * blockDim.x + threadIdx.x;
    int nS = n_nodes * IN_F;
    if (i < nS) g_S[i] = 0.0f;
    if (i < n_nodes) g_deg[i] = 0.0f;
}

// ---------------------------------------------------------------------------
// Kernel 2: scatter-accumulate edges into S with vector float4 RED atomics.
// One thread per float4 chunk: 16 threads per edge, fully coalesced e reads.
// ---------------------------------------------------------------------------
__global__ __launch_bounds__(256)
void scatter_kernel(const float4* __restrict__ e4,
                    const int* __restrict__ dst,
                    int n_edges) {
    int t = blockIdx.x * blockDim.x + threadIdx.x;
    int total = n_edges * 16;           // 64 floats / 4 per chunk
    if (t >= total) return;
    int edge = t >> 4;
    int c    = t & 15;
    int d    = __ldg(dst + edge);
    float4 v = e4[t];
    float* p = g_S + (size_t)d * IN_F + c * 4;
    asm volatile("red.global.add.v4.f32 [%0], {%1, %2, %3, %4};"
                 :: "l"(p), "f"(v.x), "f"(v.y), "f"(v.z), "f"(v.w)
                 : "memory");
    if (c == 0) atomicAdd(g_deg + d, 1.0f);   // compiles to REDG (no return)
}

// ---------------------------------------------------------------------------
// Kernel 3: h[n,o] = (S[n,:] . W[o,:]) / max(deg,1) + b[o] * (deg>0)
// Tile: 64 nodes x 100 outs per block; 160 threads; per-thread 8 nodes x 5 outs.
// W transposed in smem [k][100] (og*5 pattern is bank-conflict-free).
// ---------------------------------------------------------------------------
#define NT   64      // nodes per block
#define NG   8       // node groups (8 nodes each)
#define OG   20      // out groups (5 outs each)
#define TPB  (NG * OG)   // 160 threads
#define SS   65      // padded Ssm row stride (8*65 % 32 == 8 -> no bank clash)

__global__ __launch_bounds__(TPB)
void gemm_kernel(const float* __restrict__ W,
                 const float* __restrict__ b,
                 float* __restrict__ out,
                 int n_nodes) {
    __shared__ float Ssm[NT * SS];          // 16.6 KB
    __shared__ float Wsm[IN_F * OUT_F];     // 25.6 KB, [k][o]
    __shared__ float bsm[OUT_F];
    __shared__ float invd[NT];
    __shared__ float bfac[NT];

    int tid   = threadIdx.x;
    int node0 = blockIdx.x * NT;

    // W transpose load: Wsm[k*100 + o] = W[o*64 + k]  (coalesced global read)
    for (int i = tid; i < IN_F * OUT_F; i += TPB) {
        int o = i / IN_F, k = i % IN_F;
        Wsm[k * OUT_F + o] = W[i];
    }
    for (int i = tid; i < OUT_F; i += TPB) bsm[i] = b[i];

    // S tile load (float4 global, scalar STS into padded rows)
    for (int i = tid; i < NT * 16; i += TPB) {
        int r = i >> 4, c = i & 15;
        int node = node0 + r;
        float4 v = make_float4(0.f, 0.f, 0.f, 0.f);
        if (node < n_nodes)
            v = reinterpret_cast<const float4*>(g_S)[(size_t)node * 16 + c];
        float* p = &Ssm[r * SS + c * 4];
        p[0] = v.x; p[1] = v.y; p[2] = v.z; p[3] = v.w;
    }

    // degree -> inverse + bias mask
    for (int i = tid; i < NT; i += TPB) {
        int node = node0 + i;
        float dg = (node < n_nodes) ? g_deg[node] : 0.0f;
        invd[i] = (dg > 0.0f) ? (1.0f / dg) : 0.0f;
        bfac[i] = (dg > 0.0f) ? 1.0f : 0.0f;
    }
    __syncthreads();

    int og = tid % OG;   // 0..19 -> outs [og*5, og*5+5)
    int ng = tid / OG;   // 0..7  -> nodes [ng*8, ng*8+8)

    float acc[8][5];
#pragma unroll
    for (int j = 0; j < 8; j++)
#pragma unroll
        for (int i = 0; i < 5; i++) acc[j][i] = 0.0f;

    const float* wp = &Wsm[og * 5];
    const float* sp = &Ssm[ng * 8 * SS];

#pragma unroll 4
    for (int k = 0; k < IN_F; k++) {
        float w0 = wp[k * OUT_F + 0];
        float w1 = wp[k * OUT_F + 1];
        float w2 = wp[k * OUT_F + 2];
        float w3 = wp[k * OUT_F + 3];
        float w4 = wp[k * OUT_F + 4];
#pragma unroll
        for (int j = 0; j < 8; j++) {
            float s = sp[j * SS + k];
            acc[j][0] += s * w0;
            acc[j][1] += s * w1;
            acc[j][2] += s * w2;
            acc[j][3] += s * w3;
            acc[j][4] += s * w4;
        }
    }

    // writeback: scale by 1/deg, add masked bias
#pragma unroll
    for (int j = 0; j < 8; j++) {
        int lr   = ng * 8 + j;
        int node = node0 + lr;
        if (node >= n_nodes) continue;
        float inv = invd[lr];
        float bf  = bfac[lr];
        float* op = out + (size_t)node * OUT_F + og * 5;
#pragma unroll
        for (int i = 0; i < 5; i++)
            op[i] = acc[j][i] * inv + bsm[og * 5 + i] * bf;
    }
}

// ---------------------------------------------------------------------------
extern "C" void kernel_launch(void* const* d_in, const int* in_sizes, int n_in,
                              void* d_out, int out_size) {
    const float* e   = (const float*)d_in[0];
    const int*   dst = (const int*)d_in[1];
    const float* W   = (const float*)d_in[2];
    const float* b   = (const float*)d_in[3];
    float*       out = (float*)d_out;

    int n_edges = in_sizes[1];              // dst element count
    int n_nodes = out_size / OUT_F;         // 100000

    int zeroN = n_nodes * IN_F;             // covers both S and deg ranges
    zero_kernel<<<(zeroN + 255) / 256, 256>>>(n_nodes);

    int chunks = n_edges * 16;
    scatter_kernel<<<(chunks + 255) / 256, 256>>>(
        (const float4*)e, dst, n_edges);

    gemm_kernel<<<(n_nodes + NT - 1) / NT, TPB>>>(W, b, out, n_nodes);
}